// round 4
// baseline (speedup 1.0000x reference)
#include <cuda_runtime.h>
#include <cuda_bf16.h>

// ---------------------------------------------------------------------------
// Tree NN: reps = emb[tokens] (4096 x 128 x 128 f32)
// 7 levels: X_{l+1} = tanh( X_l.reshape(M,256) @ W_tree^T + b_tree )
// out = root @ W_cls^T + b_cls  -> (4096, 3) f32
//
// concat(left,right) of adjacent rows is a reinterpret of the row-major
// previous-level buffer: [2M,128] == [M,256]. Each level is one GEMM.
//
// Precision: bf16 3-term split (hi/lo), D = Ah*Bh + Ah*Bl + Al*Bh, fp32 accum.
// Activations stored packed: u32 = hi | (lo << 16).
// ---------------------------------------------------------------------------

#define TLK_AS 264   // A plane row stride in bf16 elems (256 + 8 pad)
#define TLK_WS 136   // W plane row stride (128 + 8 pad)
#define TLK_SMEM ((2 * 128 * TLK_AS + 2 * 128 * TLK_WS) * 2 + 256 * 4)

__device__ unsigned int g_buf0[262144u * 128u];  // 128 MiB: L1,3,5,7 outputs
__device__ unsigned int g_buf1[131072u * 128u];  //  64 MiB: L2,4,6 outputs
__device__ int g_tok64;                          // token dtype flag

// Detect token dtype: if buffer holds int64 values < 2^31, every odd 32-bit
// word is 0. Random int32 tokens make that essentially impossible.
__global__ void detect_tok_kernel(const unsigned int* __restrict__ t) {
    if (threadIdx.x == 0 && blockIdx.x == 0) {
        int all_zero = 1;
        for (int i = 1; i < 256; i += 2) all_zero &= (t[i] == 0u);
        g_tok64 = all_zero;
    }
}

__device__ __forceinline__ float fast_tanh(float x) {
    float e = __expf(2.0f * x);
    return 1.0f - __fdividef(2.0f, e + 1.0f);
}

__device__ __forceinline__ void split_store(__nv_bfloat16* Ph, __nv_bfloat16* Pl,
                                            int off, float x0, float x1) {
    __nv_bfloat16 h0 = __float2bfloat16(x0);
    __nv_bfloat16 h1 = __float2bfloat16(x1);
    __nv_bfloat16 l0 = __float2bfloat16(x0 - __bfloat162float(h0));
    __nv_bfloat16 l1 = __float2bfloat16(x1 - __bfloat162float(h1));
    unsigned int hp = (unsigned int)__bfloat16_as_ushort(h0) |
                      ((unsigned int)__bfloat16_as_ushort(h1) << 16);
    unsigned int lp = (unsigned int)__bfloat16_as_ushort(l0) |
                      ((unsigned int)__bfloat16_as_ushort(l1) << 16);
    *(unsigned int*)(Ph + off) = hp;
    *(unsigned int*)(Pl + off) = lp;
}

__device__ __forceinline__ void mma_bf16(float* d, const unsigned int* a,
                                         const unsigned int* b) {
    asm volatile(
        "mma.sync.aligned.m16n8k16.row.col.f32.bf16.bf16.f32 "
        "{%0,%1,%2,%3}, {%4,%5,%6,%7}, {%8,%9}, {%0,%1,%2,%3};\n"
        : "+f"(d[0]), "+f"(d[1]), "+f"(d[2]), "+f"(d[3])
        : "r"(a[0]), "r"(a[1]), "r"(a[2]), "r"(a[3]), "r"(b[0]), "r"(b[1]));
}

// One tree level: out[M,128] = tanh(A[M,256] @ W^T + b). Grid.x = M/128.
__global__ __launch_bounds__(256) void tree_level_kernel(
    const void* __restrict__ tokens_raw,
    const float* __restrict__ emb,
    const float* __restrict__ Wt,     // [128][256] row-major (e, h)
    const float* __restrict__ bias,   // [128]
    int first, int flip)
{
    extern __shared__ __align__(16) unsigned char smem_raw[];
    __nv_bfloat16* Ah = (__nv_bfloat16*)smem_raw;
    __nv_bfloat16* Al = Ah + 128 * TLK_AS;
    __nv_bfloat16* Wh = Al + 128 * TLK_AS;
    __nv_bfloat16* Wl = Wh + 128 * TLK_WS;
    int* sTok = (int*)(Wl + 128 * TLK_WS);

    const unsigned int* Ain = flip ? g_buf1 : g_buf0;
    unsigned int* Aout      = flip ? g_buf0 : g_buf1;

    const int tid = threadIdx.x;
    const int m0 = blockIdx.x * 128;

    // ---- stage A tile (128 rows x 256 cols) as bf16 hi/lo planes ----
    if (first) {
        long long ti = (long long)m0 * 2 + tid;
        int tok = g_tok64 ? (int)((const long long*)tokens_raw)[ti]
                          : ((const int*)tokens_raw)[ti];
        if ((unsigned)tok >= 100000u) tok = 0;   // hard OOB guard
        sTok[tid] = tok;
        __syncthreads();
#pragma unroll
        for (int i = 0; i < 32; i++) {
            int idx  = i * 256 + tid;
            int row  = idx >> 6;
            int q    = idx & 63;
            int half = q >> 5;
            int f4   = q & 31;
            int tk   = sTok[row * 2 + half];
            float4 v = __ldg((const float4*)emb + (size_t)tk * 32 + f4);
            int c = half * 128 + f4 * 4;
            split_store(Ah, Al, row * TLK_AS + c,     v.x, v.y);
            split_store(Ah, Al, row * TLK_AS + c + 2, v.z, v.w);
        }
    } else {
#pragma unroll
        for (int i = 0; i < 32; i++) {
            int idx = i * 256 + tid;
            int row = idx >> 6;
            int c4  = idx & 63;
            uint4 p = __ldg((const uint4*)Ain + (size_t)(m0 + row) * 64 + c4);
            int c = c4 * 4;
            unsigned int h01 = (p.x & 0xffffu) | (p.y << 16);
            unsigned int l01 = (p.x >> 16)     | (p.y & 0xffff0000u);
            unsigned int h23 = (p.z & 0xffffu) | (p.w << 16);
            unsigned int l23 = (p.z >> 16)     | (p.w & 0xffff0000u);
            int off = row * TLK_AS + c;
            *(unsigned int*)(Ah + off)     = h01;
            *(unsigned int*)(Al + off)     = l01;
            *(unsigned int*)(Ah + off + 2) = h23;
            *(unsigned int*)(Al + off + 2) = l23;
        }
    }

    const int lane = tid & 31;
    const int w    = tid >> 5;
    const int wm   = (w >> 1) * 32;   // 4 warps along M
    const int wn   = (w & 1) * 64;    // 2 warps along N
    const int g    = lane >> 2;
    const int t2   = lane & 3;

    float acc[2][8][4] = {};

    for (int kc = 0; kc < 2; kc++) {
        if (kc) __syncthreads();
        // ---- stage W chunk (128 e-rows x 128 k-cols) as bf16 hi/lo ----
#pragma unroll
        for (int i = 0; i < 16; i++) {
            int idx = i * 256 + tid;
            int e   = idx >> 5;
            int f4  = idx & 31;
            float4 v = __ldg((const float4*)Wt + e * 64 + kc * 32 + f4);
            int c = f4 * 4;
            split_store(Wh, Wl, e * TLK_WS + c,     v.x, v.y);
            split_store(Wh, Wl, e * TLK_WS + c + 2, v.z, v.w);
        }
        __syncthreads();

#pragma unroll 2
        for (int ks = 0; ks < 8; ks++) {
            int kb = ks * 16 + 2 * t2;
            int ka = kc * 128 + kb;
            unsigned int bh[8][2], bl[8][2];
#pragma unroll
            for (int nt = 0; nt < 8; nt++) {
                int nr = wn + nt * 8 + g;
                const __nv_bfloat16* ph = Wh + nr * TLK_WS + kb;
                const __nv_bfloat16* pl = Wl + nr * TLK_WS + kb;
                bh[nt][0] = *(const unsigned int*)ph;
                bh[nt][1] = *(const unsigned int*)(ph + 8);
                bl[nt][0] = *(const unsigned int*)pl;
                bl[nt][1] = *(const unsigned int*)(pl + 8);
            }
#pragma unroll
            for (int mt = 0; mt < 2; mt++) {
                int r0 = wm + mt * 16 + g;
                const __nv_bfloat16* ph = Ah + r0 * TLK_AS + ka;
                const __nv_bfloat16* pl = Al + r0 * TLK_AS + ka;
                unsigned int ah[4], al[4];
                ah[0] = *(const unsigned int*)ph;
                ah[1] = *(const unsigned int*)(ph + 8 * TLK_AS);
                ah[2] = *(const unsigned int*)(ph + 8);
                ah[3] = *(const unsigned int*)(ph + 8 * TLK_AS + 8);
                al[0] = *(const unsigned int*)pl;
                al[1] = *(const unsigned int*)(pl + 8 * TLK_AS);
                al[2] = *(const unsigned int*)(pl + 8);
                al[3] = *(const unsigned int*)(pl + 8 * TLK_AS + 8);
#pragma unroll
                for (int nt = 0; nt < 8; nt++) {
                    mma_bf16(acc[mt][nt], ah, bh[nt]);   // Ah*Bh
                    mma_bf16(acc[mt][nt], ah, bl[nt]);   // Ah*Bl
                    mma_bf16(acc[mt][nt], al, bh[nt]);   // Al*Bh
                }
            }
        }
    }

    // ---- epilogue: bias + tanh + re-split to packed bf16 hi/lo ----
#pragma unroll
    for (int mt = 0; mt < 2; mt++) {
#pragma unroll
        for (int nt = 0; nt < 8; nt++) {
            int col = wn + nt * 8 + 2 * t2;
            float b0 = __ldg(bias + col);
            float b1 = __ldg(bias + col + 1);
#pragma unroll
            for (int h = 0; h < 2; h++) {
                int row = m0 + wm + mt * 16 + g + h * 8;
                float v0 = fast_tanh(acc[mt][nt][h * 2 + 0] + b0);
                float v1 = fast_tanh(acc[mt][nt][h * 2 + 1] + b1);
                __nv_bfloat16 h0 = __float2bfloat16(v0);
                __nv_bfloat16 h1 = __float2bfloat16(v1);
                __nv_bfloat16 l0 = __float2bfloat16(v0 - __bfloat162float(h0));
                __nv_bfloat16 l1 = __float2bfloat16(v1 - __bfloat162float(h1));
                uint2 pk;
                pk.x = (unsigned int)__bfloat16_as_ushort(h0) |
                       ((unsigned int)__bfloat16_as_ushort(l0) << 16);
                pk.y = (unsigned int)__bfloat16_as_ushort(h1) |
                       ((unsigned int)__bfloat16_as_ushort(l1) << 16);
                *(uint2*)(Aout + (size_t)row * 128 + col) = pk;
            }
        }
    }
}

// classifier: out[b, j] = root[b,:] . W_cls[j,:] + b_cls[j]; one warp per row
__global__ __launch_bounds__(256) void cls_kernel(
    const float* __restrict__ Wc, const float* __restrict__ bc,
    float* __restrict__ out)
{
    int warp = (blockIdx.x * 256 + threadIdx.x) >> 5;
    int lane = threadIdx.x & 31;
    if (warp >= 4096) return;
    const unsigned int* root = g_buf0 + (size_t)warp * 128;
    float s0 = 0.f, s1 = 0.f, s2 = 0.f;
#pragma unroll
    for (int i = 0; i < 4; i++) {
        int e = lane + i * 32;
        unsigned int p = __ldg(root + e);
        float x = __bfloat162float(__ushort_as_bfloat16((unsigned short)(p & 0xffffu))) +
                  __bfloat162float(__ushort_as_bfloat16((unsigned short)(p >> 16)));
        s0 += x * __ldg(Wc + e);
        s1 += x * __ldg(Wc + 128 + e);
        s2 += x * __ldg(Wc + 256 + e);
    }
#pragma unroll
    for (int o = 16; o; o >>= 1) {
        s0 += __shfl_xor_sync(0xffffffffu, s0, o);
        s1 += __shfl_xor_sync(0xffffffffu, s1, o);
        s2 += __shfl_xor_sync(0xffffffffu, s2, o);
    }
    if (lane == 0) {
        out[warp * 3 + 0] = s0 + __ldg(bc + 0);
        out[warp * 3 + 1] = s1 + __ldg(bc + 1);
        out[warp * 3 + 2] = s2 + __ldg(bc + 2);
    }
}

extern "C" void kernel_launch(void* const* d_in, const int* in_sizes, int n_in,
                              void* d_out, int out_size)
{
    const void* tokens = d_in[0];
    const float* emb = (const float*)d_in[1];
    const float* Wt  = (const float*)d_in[2];
    const float* bt  = (const float*)d_in[3];
    const float* Wc  = (const float*)d_in[4];
    const float* bc  = (const float*)d_in[5];
    float* out = (float*)d_out;

    cudaFuncSetAttribute(tree_level_kernel,
                         cudaFuncAttributeMaxDynamicSharedMemorySize, TLK_SMEM);

    detect_tok_kernel<<<1, 32>>>((const unsigned int*)tokens);
    // L1: gather + GEMM, out -> buf0 (flip=1). Then alternate buffers.
    tree_level_kernel<<<2048, 256, TLK_SMEM>>>(tokens, emb, Wt, bt, 1, 1);
    tree_level_kernel<<<1024, 256, TLK_SMEM>>>(tokens, emb, Wt, bt, 0, 0);
    tree_level_kernel<<< 512, 256, TLK_SMEM>>>(tokens, emb, Wt, bt, 0, 1);
    tree_level_kernel<<< 256, 256, TLK_SMEM>>>(tokens, emb, Wt, bt, 0, 0);
    tree_level_kernel<<< 128, 256, TLK_SMEM>>>(tokens, emb, Wt, bt, 0, 1);
    tree_level_kernel<<<  64, 256, TLK_SMEM>>>(tokens, emb, Wt, bt, 0, 0);
    tree_level_kernel<<<  32, 256, TLK_SMEM>>>(tokens, emb, Wt, bt, 0, 1);
    cls_kernel<<<512, 256>>>(Wc, bc, out);
}

// round 6
// speedup vs baseline: 1.5134x; 1.5134x over previous
#include <cuda_runtime.h>
#include <cuda_bf16.h>

// ---------------------------------------------------------------------------
// Tree NN as 7 GEMMs: X_{l+1}[M,128] = tanh(X_l.view(M,256) @ W^T + b).
// concat(left,right) == reinterpret of row-major [2M,128] as [M,256].
// Precision: bf16 3-term split (hi/lo planes), D = Ah*Bh + Ah*Bl + Al*Bh.
// Activations + W stored in gmem as SEPARATE bf16 hi/lo planes so staging is
// a raw cp.async copy. ldmatrix fragment loads, double-buffered K chunks,
// M_TILE=64 -> 111KB smem -> 2 CTAs/SM.
// ---------------------------------------------------------------------------

#define STRIDE 72        // smem row stride in bf16 (64 + 8 pad)
#define A_OFF_H 0
#define A_OFF_L (64 * STRIDE)
#define W_OFF_H (2 * 64 * STRIDE)
#define W_OFF_L (2 * 64 * STRIDE + 128 * STRIDE)
#define BUF_ELE (2 * 64 * STRIDE + 2 * 128 * STRIDE)   // 27648 bf16
#define SMEM_BYTES (2 * BUF_ELE * 2 + 128 * 4)         // 111104 B

// activation planes (ping-pong) + W planes, all bf16
__device__ __nv_bfloat16 gH0[262144u * 128u];   // 64 MiB
__device__ __nv_bfloat16 gL0[262144u * 128u];   // 64 MiB
__device__ __nv_bfloat16 gH1[131072u * 128u];   // 32 MiB
__device__ __nv_bfloat16 gL1[131072u * 128u];   // 32 MiB
__device__ __nv_bfloat16 gWh[128 * 256];
__device__ __nv_bfloat16 gWl[128 * 256];
__device__ int g_tok64;

__global__ void detect_tok_kernel(const unsigned int* __restrict__ t) {
    if (threadIdx.x == 0) {
        int all_zero = 1;
        for (int i = 1; i < 256; i += 2) all_zero &= (t[i] == 0u);
        g_tok64 = all_zero;
    }
}

// split W (f32 [128][256]) into bf16 hi/lo planes, once per launch
__global__ void wsplit_kernel(const float* __restrict__ Wt) {
    int i = blockIdx.x * 256 + threadIdx.x;
    if (i < 128 * 256) {
        float v = Wt[i];
        __nv_bfloat16 h = __float2bfloat16(v);
        gWh[i] = h;
        gWl[i] = __float2bfloat16(v - __bfloat162float(h));
    }
}

__device__ __forceinline__ float fast_tanh(float x) {
    float e = __expf(2.0f * x);
    return 1.0f - __fdividef(2.0f, e + 1.0f);
}

__device__ __forceinline__ void mma_bf16(float* d, const unsigned int* a,
                                         const unsigned int* b) {
    asm volatile(
        "mma.sync.aligned.m16n8k16.row.col.f32.bf16.bf16.f32 "
        "{%0,%1,%2,%3}, {%4,%5,%6,%7}, {%8,%9}, {%0,%1,%2,%3};\n"
        : "+f"(d[0]), "+f"(d[1]), "+f"(d[2]), "+f"(d[3])
        : "r"(a[0]), "r"(a[1]), "r"(a[2]), "r"(a[3]), "r"(b[0]), "r"(b[1]));
}

__device__ __forceinline__ void ldsm4(unsigned int* r, unsigned int saddr) {
    asm volatile(
        "ldmatrix.sync.aligned.m8n8.x4.shared.b16 {%0,%1,%2,%3}, [%4];\n"
        : "=r"(r[0]), "=r"(r[1]), "=r"(r[2]), "=r"(r[3]) : "r"(saddr));
}

__device__ __forceinline__ void cpa16(unsigned int dst, const void* src) {
    asm volatile("cp.async.cg.shared.global [%0], [%1], 16;\n"
                 :: "r"(dst), "l"(src));
}
__device__ __forceinline__ void cpa_commit() {
    asm volatile("cp.async.commit_group;\n");
}
__device__ __forceinline__ void cpa_wait1() {
    asm volatile("cp.async.wait_group 1;\n");
}

// One level. Grid.x = M/64, 256 threads, 2 CTAs/SM.
__global__ __launch_bounds__(256, 2) void tree_level_kernel(
    const void* __restrict__ tokens_raw,
    const float* __restrict__ emb,
    const float* __restrict__ bias,
    int first, int flip)
{
    extern __shared__ __align__(16) __nv_bfloat16 smem[];
    int* sTok = (int*)(smem + 2 * BUF_ELE);
    const unsigned int sbase = (unsigned int)__cvta_generic_to_shared(smem);

    const __nv_bfloat16* AinH = flip ? gH1 : gH0;
    const __nv_bfloat16* AinL = flip ? gL1 : gL0;
    __nv_bfloat16* AoutH = flip ? gH0 : gH1;
    __nv_bfloat16* AoutL = flip ? gL0 : gL1;

    const int tid = threadIdx.x;
    const int m0 = blockIdx.x * 64;

    // ---- gather setup (level 1 only) ----
    if (first) {
        if (tid < 128) {
            long long ti = (long long)m0 * 2 + tid;
            int tok = g_tok64 ? (int)((const long long*)tokens_raw)[ti]
                              : ((const int*)tokens_raw)[ti];
            if ((unsigned)tok >= 100000u) tok = 0;
            sTok[tid] = tok;
        }
        __syncthreads();
    }

    const int grow  = tid >> 2;        // gather row 0..63
    const int gslot = tid & 3;         // 4 float4 slots per thread

    float4 R[4];                       // gather prefetch registers

    // --- staging helpers ---
    auto stageW = [&](int c, int buf) {
        unsigned int b = sbase + (buf * BUF_ELE) * 2;
#pragma unroll
        for (int i = 0; i < 4; i++) {
            int idx = i * 256 + tid;           // 1024 chunks
            int row = idx >> 3, s = idx & 7;
            int ge = row * 256 + c * 64 + s * 8;
            unsigned int so = (unsigned int)(row * STRIDE + s * 8) * 2;
            cpa16(b + (W_OFF_H * 2) + so, gWh + ge);
            cpa16(b + (W_OFF_L * 2) + so, gWl + ge);
        }
    };
    auto stageA = [&](int c, int buf) {
        unsigned int b = sbase + (buf * BUF_ELE) * 2;
#pragma unroll
        for (int i = 0; i < 2; i++) {
            int idx = i * 256 + tid;           // 512 chunks
            int row = idx >> 3, s = idx & 7;
            size_t ge = (size_t)(m0 + row) * 256 + c * 64 + s * 8;
            unsigned int so = (unsigned int)(row * STRIDE + s * 8) * 2;
            cpa16(b + (A_OFF_H * 2) + so, AinH + ge);
            cpa16(b + (A_OFF_L * 2) + so, AinL + ge);
        }
    };
    auto gatherLd = [&](int c) {
        int tok = sTok[grow * 2 + (c >> 1)];
        const float4* src = (const float4*)emb + (size_t)tok * 32 + (c & 1) * 16;
#pragma unroll
        for (int j = 0; j < 4; j++) R[j] = __ldg(src + gslot + j * 4);
    };
    auto gatherSt = [&](int buf) {
        __nv_bfloat16* Ah = smem + buf * BUF_ELE + A_OFF_H;
        __nv_bfloat16* Al = smem + buf * BUF_ELE + A_OFF_L;
#pragma unroll
        for (int j = 0; j < 4; j++) {
            int col = (gslot + j * 4) * 4;
            float x[4] = {R[j].x, R[j].y, R[j].z, R[j].w};
            unsigned int hp[2], lp[2];
#pragma unroll
            for (int q = 0; q < 2; q++) {
                __nv_bfloat16 h0 = __float2bfloat16(x[2*q]);
                __nv_bfloat16 h1 = __float2bfloat16(x[2*q+1]);
                __nv_bfloat16 l0 = __float2bfloat16(x[2*q]   - __bfloat162float(h0));
                __nv_bfloat16 l1 = __float2bfloat16(x[2*q+1] - __bfloat162float(h1));
                hp[q] = (unsigned)__bfloat16_as_ushort(h0) |
                        ((unsigned)__bfloat16_as_ushort(h1) << 16);
                lp[q] = (unsigned)__bfloat16_as_ushort(l0) |
                        ((unsigned)__bfloat16_as_ushort(l1) << 16);
            }
            *(uint2*)(Ah + grow * STRIDE + col) = make_uint2(hp[0], hp[1]);
            *(uint2*)(Al + grow * STRIDE + col) = make_uint2(lp[0], lp[1]);
        }
    };

    // ---- pipeline prologue: stage chunks 0,1 ----
    if (first) {
        gatherLd(0); stageW(0, 0); cpa_commit(); gatherSt(0);
        gatherLd(1); stageW(1, 1); cpa_commit(); gatherSt(1);
        gatherLd(2);
    } else {
        stageA(0, 0); stageW(0, 0); cpa_commit();
        stageA(1, 1); stageW(1, 1); cpa_commit();
    }

    // ---- warp/fragment geometry ----
    const int lane = tid & 31;
    const int w    = tid >> 5;
    const int wm   = (w >> 2) * 32;          // 2 warps along M
    const int wn   = (w & 3) * 32;           // 4 warps along N
    const int la_row = lane & 15;
    const int la_col = (lane >> 4) << 3;
    const int lb_n   = ((lane >> 4) << 3) + (lane & 7);
    const int lb_kh  = ((lane >> 3) & 1) << 3;

    float acc[2][4][4] = {};

    for (int c = 0; c < 4; c++) {
        cpa_wait1();
        __syncthreads();
        const int buf = c & 1;
        const unsigned int bB = sbase + (buf * BUF_ELE) * 2;
#pragma unroll
        for (int ks = 0; ks < 4; ks++) {
            unsigned int ah[2][4], al[2][4], bh[2][4], bl[2][4];
#pragma unroll
            for (int mt = 0; mt < 2; mt++) {
                unsigned int ro = (unsigned)((wm + mt*16 + la_row) * STRIDE
                                             + ks*16 + la_col) * 2;
                ldsm4(ah[mt], bB + A_OFF_H * 2 + ro);
                ldsm4(al[mt], bB + A_OFF_L * 2 + ro);
            }
#pragma unroll
            for (int pr = 0; pr < 2; pr++) {
                unsigned int ro = (unsigned)((wn + pr*16 + lb_n) * STRIDE
                                             + ks*16 + lb_kh) * 2;
                ldsm4(bh[pr], bB + W_OFF_H * 2 + ro);
                ldsm4(bl[pr], bB + W_OFF_L * 2 + ro);
            }
#pragma unroll
            for (int mt = 0; mt < 2; mt++)
#pragma unroll
                for (int nt = 0; nt < 4; nt++) {
                    const unsigned int* bhp = &bh[nt >> 1][(nt & 1) * 2];
                    const unsigned int* blp = &bl[nt >> 1][(nt & 1) * 2];
                    mma_bf16(acc[mt][nt], ah[mt], bhp);
                    mma_bf16(acc[mt][nt], ah[mt], blp);
                    mma_bf16(acc[mt][nt], al[mt], bhp);
                }
        }
        __syncthreads();
        if (c < 2) {
            if (first) { stageW(c + 2, buf); cpa_commit(); gatherSt(buf);
                         if (c == 0) gatherLd(3); }
            else       { stageA(c + 2, buf); stageW(c + 2, buf); cpa_commit(); }
        } else {
            cpa_commit();   // empty group keeps wait count consistent
        }
    }

    // ---- epilogue: bias + tanh + split to hi/lo planes ----
    const int g  = lane >> 2;
    const int t2 = lane & 3;
#pragma unroll
    for (int mt = 0; mt < 2; mt++)
#pragma unroll
        for (int nt = 0; nt < 4; nt++) {
            int col = wn + nt * 8 + 2 * t2;
            float b0 = __ldg(bias + col);
            float b1 = __ldg(bias + col + 1);
#pragma unroll
            for (int h = 0; h < 2; h++) {
                size_t row = (size_t)m0 + wm + mt * 16 + g + h * 8;
                float v0 = fast_tanh(acc[mt][nt][h * 2 + 0] + b0);
                float v1 = fast_tanh(acc[mt][nt][h * 2 + 1] + b1);
                __nv_bfloat16 h0 = __float2bfloat16(v0);
                __nv_bfloat16 h1 = __float2bfloat16(v1);
                __nv_bfloat16 l0 = __float2bfloat16(v0 - __bfloat162float(h0));
                __nv_bfloat16 l1 = __float2bfloat16(v1 - __bfloat162float(h1));
                unsigned int hp = (unsigned)__bfloat16_as_ushort(h0) |
                                  ((unsigned)__bfloat16_as_ushort(h1) << 16);
                unsigned int lp = (unsigned)__bfloat16_as_ushort(l0) |
                                  ((unsigned)__bfloat16_as_ushort(l1) << 16);
                *(unsigned int*)(AoutH + row * 128 + col) = hp;
                *(unsigned int*)(AoutL + row * 128 + col) = lp;
            }
        }
}

// classifier: out[b,j] = (hi+lo root row b) . W_cls[j] + b_cls[j]
__global__ __launch_bounds__(256) void cls_kernel(
    const float* __restrict__ Wc, const float* __restrict__ bc,
    float* __restrict__ out)
{
    int warp = (blockIdx.x * 256 + threadIdx.x) >> 5;
    int lane = threadIdx.x & 31;
    if (warp >= 4096) return;
    size_t base = (size_t)warp * 128;
    float s0 = 0.f, s1 = 0.f, s2 = 0.f;
#pragma unroll
    for (int i = 0; i < 4; i++) {
        int e = lane + i * 32;
        float x = __bfloat162float(gH0[base + e]) + __bfloat162float(gL0[base + e]);
        s0 += x * __ldg(Wc + e);
        s1 += x * __ldg(Wc + 128 + e);
        s2 += x * __ldg(Wc + 256 + e);
    }
#pragma unroll
    for (int o = 16; o; o >>= 1) {
        s0 += __shfl_xor_sync(0xffffffffu, s0, o);
        s1 += __shfl_xor_sync(0xffffffffu, s1, o);
        s2 += __shfl_xor_sync(0xffffffffu, s2, o);
    }
    if (lane == 0) {
        out[warp * 3 + 0] = s0 + __ldg(bc + 0);
        out[warp * 3 + 1] = s1 + __ldg(bc + 1);
        out[warp * 3 + 2] = s2 + __ldg(bc + 2);
    }
}

extern "C" void kernel_launch(void* const* d_in, const int* in_sizes, int n_in,
                              void* d_out, int out_size)
{
    const void* tokens = d_in[0];
    const float* emb = (const float*)d_in[1];
    const float* Wt  = (const float*)d_in[2];
    const float* bt  = (const float*)d_in[3];
    const float* Wc  = (const float*)d_in[4];
    const float* bc  = (const float*)d_in[5];
    float* out = (float*)d_out;

    cudaFuncSetAttribute(tree_level_kernel,
                         cudaFuncAttributeMaxDynamicSharedMemorySize, SMEM_BYTES);

    detect_tok_kernel<<<1, 32>>>((const unsigned int*)tokens);
    wsplit_kernel<<<128, 256>>>(Wt);
    // L1 gather -> planes0; then alternate.  grid = M/64
    tree_level_kernel<<<4096, 256, SMEM_BYTES>>>(tokens, emb, bt, 1, 1);
    tree_level_kernel<<<2048, 256, SMEM_BYTES>>>(tokens, emb, bt, 0, 0);
    tree_level_kernel<<<1024, 256, SMEM_BYTES>>>(tokens, emb, bt, 0, 1);
    tree_level_kernel<<< 512, 256, SMEM_BYTES>>>(tokens, emb, bt, 0, 0);
    tree_level_kernel<<< 256, 256, SMEM_BYTES>>>(tokens, emb, bt, 0, 1);
    tree_level_kernel<<< 128, 256, SMEM_BYTES>>>(tokens, emb, bt, 0, 0);
    tree_level_kernel<<<  64, 256, SMEM_BYTES>>>(tokens, emb, bt, 0, 1);
    cls_kernel<<<512, 256>>>(Wc, bc, out);
}